// round 14
// baseline (speedup 1.0000x reference)
#include <cuda_runtime.h>

// ---------------------------------------------------------------------------
// WEFPositionalEncoding fused single kernel:
//   out[b,s,d] = x[b,s,d] + pos[s,d]
// pos row recomputed per block (cheap: 624-term lattice sum + 4->D proj + LN),
// hidden behind cp.async staging of the 8 x-rows this block processes.
// B=64, H=W=24, S=577, D=1024.
// ---------------------------------------------------------------------------

#define OMEGA1F 2.62205755429212f
#define BPB 8          // batch elements per block

__device__ __forceinline__ float clampf(float v, float lim) {
    return fminf(fmaxf(v, -lim), lim);
}

__device__ __forceinline__ float warp_sum(float v) {
    #pragma unroll
    for (int o = 16; o > 0; o >>= 1) v += __shfl_xor_sync(0xFFFFFFFFu, v, o);
    return v;
}

__global__ void __launch_bounds__(256) fused_kernel(
    const float4* __restrict__ x, float4* __restrict__ out,
    const float* __restrict__ las_p, const float* __restrict__ al_p,
    const float* __restrict__ pw,    const float* __restrict__ pb,
    const float* __restrict__ lg,    const float* __restrict__ lb,
    const float4* __restrict__ cls,  const float* __restrict__ ps_p,
    int H, int W, int S, int Dq, int B)
{
    __shared__ float4 sx[BPB * 256];          // 32 KB staging for x rows
    __shared__ float4 wpart[8];
    __shared__ float  fsh[4];
    __shared__ float  stats[2];

    const int s    = blockIdx.x;
    const int b0   = blockIdx.y * BPB;
    const int tid  = threadIdx.x;
    const int wid  = tid >> 5;
    const int lane = tid & 31;
    const int nb   = (b0 + BPB <= B) ? BPB : (B - b0);

    const size_t stride = (size_t)S * Dq;     // float4 stride between batches
    const size_t base   = (size_t)b0 * stride + (size_t)s * Dq + tid;

    // ---- 1) issue async copies of all x rows this block handles ----
    #pragma unroll
    for (int k = 0; k < BPB; k++) {
        if (k < nb) {
            unsigned saddr = (unsigned)__cvta_generic_to_shared(&sx[k * 256 + tid]);
            const float4* g = x + base + (size_t)k * stride;
            asm volatile("cp.async.cg.shared.global [%0], [%1], 16;\n"
                         :: "r"(saddr), "l"(g));
        }
    }
    asm volatile("cp.async.commit_group;\n");

    // ---- 2) compute this thread's pos float4 (dims 4*tid .. 4*tid+3) ----
    const float ps = ps_p[0];
    float4 pv;

    if (s == 0) {
        const float4 c = cls[tid];
        pv = make_float4(c.x * ps, c.y * ps, c.z * ps, c.w * ps);
    } else {
        const int pt  = s - 1;
        const int row = pt / W;
        const int col = pt % W;

        const float al = al_p[0];
        float spl = (al > 20.0f) ? al : log1pf(expf(al));
        spl = fminf(fmaxf(spl, 0.02f), 8.0f);

        const float zr = ((col + 0.5f) / (float)W) * (2.0f * OMEGA1F) * 0.4f;
        const float zi = ((row + 0.5f) / (float)H) * (2.0f * spl) * 0.4f;

        // lattice sum over 624 points, strided across 256 threads
        float swr = 0.f, swi = 0.f, spr = 0.f, spi = 0.f;
        for (int l = tid; l < 624; l += 256) {
            const int l2 = (l < 312) ? l : l + 1;       // skip (0,0)
            const int m = l2 / 25 - 12;
            const int n = l2 % 25 - 12;
            const float wr = 2.0f * (float)m * OMEGA1F;
            const float wi = 2.0f * (float)n * OMEGA1F;

            const float dr = zr - wr, di = zi - wi;
            const float r2 = dr * dr + di * di;
            const float ir = 1.0f / r2;
            const float i2 = ir * ir;
            const float a = (dr * dr - di * di) * i2;   // Re 1/d^2
            const float b = (-2.0f * dr * di) * i2;     // Im 1/d^2

            const float w2  = wr * wr + wi * wi;
            const float iw  = 1.0f / w2;
            const float iw2 = iw * iw;
            const float cwr = (wr * wr - wi * wi) * iw2;
            const float cwi = (-2.0f * wr * wi) * iw2;

            swr += clampf(a - cwr, 5000.0f);
            swi += clampf(b - cwi, 5000.0f);
            spr += clampf(-2.0f * ir * (a * dr + b * di), 5000.0f);
            spi += clampf(-2.0f * ir * (b * dr - a * di), 5000.0f);
        }
        swr = warp_sum(swr); swi = warp_sum(swi);
        spr = warp_sum(spr); spi = warp_sum(spi);
        if (lane == 0) wpart[wid] = make_float4(swr, swi, spr, spi);
        __syncthreads();
        if (tid == 0) {
            float4 sm = wpart[0];
            #pragma unroll
            for (int i = 1; i < 8; i++) {
                sm.x += wpart[i].x; sm.y += wpart[i].y;
                sm.z += wpart[i].z; sm.w += wpart[i].w;
            }
            const float r2 = zr * zr + zi * zi;
            const float ir = 1.0f / r2;
            const float i2 = ir * ir;
            const float a = (zr * zr - zi * zi) * i2;
            const float b = (-2.0f * zr * zi) * i2;
            const float wpre = clampf(a + sm.x, 10000.0f);
            const float wpim = clampf(b + sm.y, 10000.0f);
            const float ppre = clampf(-2.0f * ir * (a * zr + b * zi) + sm.z, 10000.0f);
            const float ppim = clampf(-2.0f * ir * (b * zr - a * zi) + sm.w, 10000.0f);

            const float alpha = fminf(fmaxf(expf(las_p[0]), 0.002f), 0.8f);
            fsh[0] = tanhf(alpha * wpre);
            fsh[1] = tanhf(alpha * wpim);
            fsh[2] = tanhf(alpha * ppre);
            fsh[3] = tanhf(alpha * ppim);
        }
        __syncthreads();

        // projection (4 -> D) for this thread's 4 dims + block LayerNorm
        const float f0 = fsh[0], f1 = fsh[1], f2 = fsh[2], f3 = fsh[3];
        const int D = Dq * 4;
        const float4 w0 = ((const float4*)pw)[tid];
        const float4 w1 = ((const float4*)(pw + D))[tid];
        const float4 w2 = ((const float4*)(pw + 2 * D))[tid];
        const float4 w3 = ((const float4*)(pw + 3 * D))[tid];
        const float4 bb = ((const float4*)pb)[tid];
        float p0 = f0 * w0.x + f1 * w1.x + f2 * w2.x + f3 * w3.x + bb.x;
        float p1 = f0 * w0.y + f1 * w1.y + f2 * w2.y + f3 * w3.y + bb.y;
        float p2 = f0 * w0.z + f1 * w1.z + f2 * w2.z + f3 * w3.z + bb.z;
        float p3 = f0 * w0.w + f1 * w1.w + f2 * w2.w + f3 * w3.w + bb.w;

        float sum   = p0 + p1 + p2 + p3;
        float sumsq = p0 * p0 + p1 * p1 + p2 * p2 + p3 * p3;
        sum   = warp_sum(sum);
        sumsq = warp_sum(sumsq);
        if (lane == 0) wpart[wid] = make_float4(sum, sumsq, 0.f, 0.f);
        __syncthreads();
        if (tid == 0) {
            float s1 = 0.f, s2 = 0.f;
            #pragma unroll
            for (int i = 0; i < 8; i++) { s1 += wpart[i].x; s2 += wpart[i].y; }
            const float mu  = s1 / (float)D;
            const float var = s2 / (float)D - mu * mu;
            stats[0] = mu;
            stats[1] = rsqrtf(var + 1e-5f);
        }
        __syncthreads();
        const float mu = stats[0], rstd = stats[1];
        const float4 g = ((const float4*)lg)[tid];
        const float4 be = ((const float4*)lb)[tid];
        pv = make_float4(((p0 - mu) * rstd * g.x + be.x) * ps,
                         ((p1 - mu) * rstd * g.y + be.y) * ps,
                         ((p2 - mu) * rstd * g.z + be.z) * ps,
                         ((p3 - mu) * rstd * g.w + be.w) * ps);
    }

    // ---- 3) wait for staged x, add, store ----
    asm volatile("cp.async.wait_group 0;\n" ::: "memory");
    // each thread reads only its own staged slots — no block sync needed
    #pragma unroll
    for (int k = 0; k < BPB; k++) {
        if (k < nb) {
            const float4 xv = sx[k * 256 + tid];
            out[base + (size_t)k * stride] =
                make_float4(xv.x + pv.x, xv.y + pv.y, xv.z + pv.z, xv.w + pv.w);
        }
    }
}

extern "C" void kernel_launch(void* const* d_in, const int* in_sizes, int n_in,
                              void* d_out, int out_size)
{
    int iX = 0, iLAS = 3, iAL = 4, iPW = 5, iPB = 6, iLG = 7, iLB = 8, iCLS = 9, iPS = 10;
    if (n_in == 9) {
        iLAS = 1; iAL = 2; iPW = 3; iPB = 4; iLG = 5; iLB = 6; iCLS = 7; iPS = 8;
    }

    const int H = 24, W = 24;
    const int S = H * W + 1;                       // 577
    const int D = in_sizes[iCLS];                  // 1024
    const long long total = (long long)in_sizes[iX];
    const int B = (int)(total / ((long long)S * D));
    const int Dq = D / 4;

    dim3 grid(S, (B + BPB - 1) / BPB);
    fused_kernel<<<grid, Dq>>>(
        (const float4*)d_in[iX], (float4*)d_out,
        (const float*)d_in[iLAS], (const float*)d_in[iAL],
        (const float*)d_in[iPW],  (const float*)d_in[iPB],
        (const float*)d_in[iLG],  (const float*)d_in[iLB],
        (const float4*)d_in[iCLS], (const float*)d_in[iPS],
        H, W, S, Dq, B);
}